// round 1
// baseline (speedup 1.0000x reference)
#include <cuda_runtime.h>
#include <cuda_bf16.h>
#include <math.h>

// Fused FastGuidedFilter:
//   box3x3(replicate) on lr_x, lr_y, lr_x*lr_y, lr_x*lr_x -> A, b
//   8 directional 3x3 convs (zero pad) of A, b
//   d_k = convA_k*im + convb_k - im ; pick argmin |d_k| (first min wins)
//   out = clip(trunc(c_kmin), 0, 255)
// hr_x is unused by the reference -> never read.

#define TX 32
#define TY 32
#define IW 36   // input tile (TX+4) with 2-halo
#define AW 34   // A/b tile (TX+2) with 1-halo

__global__ __launch_bounds__(256, 4)
void fgf_kernel(const float* __restrict__ lrx,
                const float* __restrict__ lry,
                float* __restrict__ out,
                int H, int W)
{
    __shared__ float sx[IW * IW];
    __shared__ float sy[IW * IW];
    __shared__ float sA[AW * AW];
    __shared__ float sB[AW * AW];

    const int c   = blockIdx.z;
    const int gx0 = blockIdx.x * TX;
    const int gy0 = blockIdx.y * TY;
    const float* __restrict__ px = lrx + (size_t)c * H * W;
    const float* __restrict__ py = lry + (size_t)c * H * W;

    const int tid = threadIdx.y * 32 + threadIdx.x;

    // ---- stage 1: load 36x36 halo tile (clamped indices == replicate pad) ----
    for (int i = tid; i < IW * IW; i += 256) {
        int r = i / IW;
        int q = i - r * IW;
        int gy = gy0 + r - 2; gy = max(0, min(H - 1, gy));
        int gx = gx0 + q - 2; gx = max(0, min(W - 1, gx));
        size_t g = (size_t)gy * W + gx;
        sx[i] = px[g];
        sy[i] = py[g];
    }
    __syncthreads();

    // ---- stage 2: A,b on 34x34 (zero outside image: directional conv zero-pad) ----
    const float inv9 = 1.0f / 9.0f;
    for (int i = tid; i < AW * AW; i += 256) {
        int r = i / AW;
        int q = i - r * AW;
        int gy = gy0 + r - 1;
        int gx = gx0 + q - 1;
        float A = 0.0f, B = 0.0f;
        if (gy >= 0 && gy < H && gx >= 0 && gx < W) {
            float s1 = 0.f, s2 = 0.f, s3 = 0.f, s4 = 0.f;
            #pragma unroll
            for (int u = 0; u < 3; ++u) {
                int base = (r + u) * IW + q;
                #pragma unroll
                for (int v = 0; v < 3; ++v) {
                    float x = sx[base + v];
                    float y = sy[base + v];
                    s1 += x; s2 += y;
                    s3 += x * y; s4 += x * x;
                }
            }
            float mx  = s1 * inv9;
            float my  = s2 * inv9;
            float mxy = s3 * inv9;
            float mxx = s4 * inv9;
            A = (mxy - mx * my) / (mxx - mx * mx + 1e-4f);
            B = my - A * mx;
        }
        sA[i] = A;
        sB[i] = B;
    }
    __syncthreads();

    // ---- stage 3: 8 directional convs + argmin residual per output pixel ----
    float* __restrict__ po = out + (size_t)c * H * W;
    const float i6 = 1.0f / 6.0f;
    const float i4 = 0.25f;

    #pragma unroll
    for (int rr = 0; rr < 4; ++rr) {
        const int oy = threadIdx.y + 8 * rr;   // 0..31
        const int ox = threadIdx.x;            // 0..31

        float hlA[3], hrA[3], haA[3];
        float hlB[3], hrB[3], haB[3];
        #pragma unroll
        for (int u = 0; u < 3; ++u) {
            int base = (oy + u) * AW + ox;
            float a0 = sA[base], a1 = sA[base + 1], a2 = sA[base + 2];
            float b0 = sB[base], b1 = sB[base + 1], b2 = sB[base + 2];
            hlA[u] = a0 + a1; hrA[u] = a1 + a2; haA[u] = hlA[u] + a2;
            hlB[u] = b0 + b1; hrB[u] = b1 + b2; haB[u] = hlB[u] + b2;
        }

        float cA[8], cB[8];
        cA[0] = (hlA[0] + hlA[1] + hlA[2]) * i6;  cB[0] = (hlB[0] + hlB[1] + hlB[2]) * i6; // L
        cA[1] = (hrA[0] + hrA[1] + hrA[2]) * i6;  cB[1] = (hrB[0] + hrB[1] + hrB[2]) * i6; // R
        cA[2] = (haA[0] + haA[1]) * i6;           cB[2] = (haB[0] + haB[1]) * i6;          // U
        cA[3] = (haA[1] + haA[2]) * i6;           cB[3] = (haB[1] + haB[2]) * i6;          // D
        cA[4] = (hlA[0] + hlA[1]) * i4;           cB[4] = (hlB[0] + hlB[1]) * i4;          // NW
        cA[5] = (hrA[0] + hrA[1]) * i4;           cB[5] = (hrB[0] + hrB[1]) * i4;          // NE
        cA[6] = (hlA[1] + hlA[2]) * i4;           cB[6] = (hlB[1] + hlB[2]) * i4;          // SW
        cA[7] = (hrA[1] + hrA[2]) * i4;           cB[7] = (hrB[1] + hrB[2]) * i4;          // SE

        const float im = sx[(oy + 2) * IW + (ox + 2)];

        float best = 3.4e38f;
        float val  = 0.0f;
        #pragma unroll
        for (int k = 0; k < 8; ++k) {
            float ck = cA[k] * im + cB[k];
            float dk = fabsf(ck - im);
            if (dk < best) { best = dk; val = ck; }  // strict <: first min wins (jnp.argmin)
        }

        float r = truncf(val);
        r = fminf(fmaxf(r, 0.0f), 255.0f);
        po[(size_t)(gy0 + oy) * W + (gx0 + ox)] = r;
    }
}

extern "C" void kernel_launch(void* const* d_in, const int* in_sizes, int n_in,
                              void* d_out, int out_size)
{
    const float* lrx = (const float*)d_in[0];
    const float* lry = (const float*)d_in[1];
    // d_in[2] (hr_x) is unused by the reference computation.
    float* out = (float*)d_out;

    const int H = 2048, W = 2048;
    dim3 block(32, 8);
    dim3 grid(W / TX, H / TY, 3);
    fgf_kernel<<<grid, block>>>(lrx, lry, out, H, W);
}

// round 2
// speedup vs baseline: 1.6149x; 1.6149x over previous
#include <cuda_runtime.h>
#include <cuda_bf16.h>
#include <math.h>

// Fused FastGuidedFilter, 2x2-coarsened, float2 smem access.
//   box3x3(replicate) on lr_x, lr_y, xy, xx -> A, b   (stage 2)
//   8 directional 3x3 convs (zero pad) of A, b; argmin residual (stage 3)
//   out = clip(trunc(best), 0, 255).  hr_x unused by reference.

#define TILE 32
#define SXW  36   // input smem row stride (36x36 tile, 2-halo)
#define SAW  36   // A/b smem row stride (34 rows used, 1-halo)

__global__ __launch_bounds__(256, 3)
void fgf_kernel(const float* __restrict__ lrx,
                const float* __restrict__ lry,
                float* __restrict__ out,
                int H, int W)
{
    __shared__ float sx[36 * SXW];
    __shared__ float sy[36 * SXW];
    __shared__ float sA[34 * SAW];
    __shared__ float sB[34 * SAW];

    const int tid = threadIdx.x;
    const int c   = blockIdx.z;
    const int gx0 = blockIdx.x * TILE;
    const int gy0 = blockIdx.y * TILE;
    const float* __restrict__ px = lrx + (size_t)c * H * W;
    const float* __restrict__ py = lry + (size_t)c * H * W;

    const bool xin = (blockIdx.x > 0) && (blockIdx.x < gridDim.x - 1);
    const bool yin = (blockIdx.y > 0) && (blockIdx.y < gridDim.y - 1);

    // ---- stage 1: load 36x36 halo tile (clamp == replicate pad) ----
    if (xin) {
        // fast path: no x-clamping needed, float2 loads (gx0-2 is even -> 8B aligned)
        #pragma unroll
        for (int it = 0; it < 3; ++it) {
            int i = tid + it * 256;
            if (i < 648) {
                int r = i / 18;
                int q = (i - r * 18) * 2;
                int gy = gy0 + r - 2; gy = max(0, min(H - 1, gy));
                const float2 vx = *(const float2*)(px + (size_t)gy * W + (gx0 - 2) + q);
                const float2 vy = *(const float2*)(py + (size_t)gy * W + (gx0 - 2) + q);
                *(float2*)&sx[r * SXW + q] = vx;
                *(float2*)&sy[r * SXW + q] = vy;
            }
        }
    } else {
        for (int i = tid; i < 1296; i += 256) {
            int r = i / 36;
            int q = i - r * 36;
            int gy = gy0 + r - 2; gy = max(0, min(H - 1, gy));
            int gx = gx0 + q - 2; gx = max(0, min(W - 1, gx));
            size_t g = (size_t)gy * W + gx;
            sx[r * SXW + q] = px[g];
            sy[r * SXW + q] = py[g];
        }
    }
    __syncthreads();

    // ---- stage 2: A,b on 34x34 grid, 2x2 per thread ----
    const bool inner = xin && yin;
    #pragma unroll
    for (int it = 0; it < 2; ++it) {
        int ci = tid + it * 256;
        if (ci < 289) {                       // 17x17 chunks of 2x2
            int cr = ci / 17;
            int cq = ci - cr * 17;
            int r0 = cr * 2, q0 = cq * 2;

            float xv[4][4], yv[4][4];
            #pragma unroll
            for (int u = 0; u < 4; ++u) {
                const float* bx = &sx[(r0 + u) * SXW + q0];
                const float* by = &sy[(r0 + u) * SXW + q0];
                float2 x01 = *(const float2*)bx;
                float2 x23 = *(const float2*)(bx + 2);
                float2 y01 = *(const float2*)by;
                float2 y23 = *(const float2*)(by + 2);
                xv[u][0] = x01.x; xv[u][1] = x01.y; xv[u][2] = x23.x; xv[u][3] = x23.y;
                yv[u][0] = y01.x; yv[u][1] = y01.y; yv[u][2] = y23.x; yv[u][3] = y23.y;
            }

            float SX[2][2], SY[2][2], SXY[2][2], SXX[2][2];
            {   // x box sums
                float v0[4], v1[4];
                #pragma unroll
                for (int v = 0; v < 4; ++v) { float m = xv[1][v] + xv[2][v]; v0[v] = xv[0][v] + m; v1[v] = m + xv[3][v]; }
                float m0 = v0[1] + v0[2], m1 = v1[1] + v1[2];
                SX[0][0] = v0[0] + m0; SX[0][1] = m0 + v0[3];
                SX[1][0] = v1[0] + m1; SX[1][1] = m1 + v1[3];
            }
            {   // y box sums
                float v0[4], v1[4];
                #pragma unroll
                for (int v = 0; v < 4; ++v) { float m = yv[1][v] + yv[2][v]; v0[v] = yv[0][v] + m; v1[v] = m + yv[3][v]; }
                float m0 = v0[1] + v0[2], m1 = v1[1] + v1[2];
                SY[0][0] = v0[0] + m0; SY[0][1] = m0 + v0[3];
                SY[1][0] = v1[0] + m1; SY[1][1] = m1 + v1[3];
            }
            {   // xy box sums
                float v0[4], v1[4];
                #pragma unroll
                for (int v = 0; v < 4; ++v) {
                    float p0 = xv[0][v] * yv[0][v], p1 = xv[1][v] * yv[1][v];
                    float p2 = xv[2][v] * yv[2][v], p3 = xv[3][v] * yv[3][v];
                    float m = p1 + p2; v0[v] = p0 + m; v1[v] = m + p3;
                }
                float m0 = v0[1] + v0[2], m1 = v1[1] + v1[2];
                SXY[0][0] = v0[0] + m0; SXY[0][1] = m0 + v0[3];
                SXY[1][0] = v1[0] + m1; SXY[1][1] = m1 + v1[3];
            }
            {   // xx box sums
                float v0[4], v1[4];
                #pragma unroll
                for (int v = 0; v < 4; ++v) {
                    float p0 = xv[0][v] * xv[0][v], p1 = xv[1][v] * xv[1][v];
                    float p2 = xv[2][v] * xv[2][v], p3 = xv[3][v] * xv[3][v];
                    float m = p1 + p2; v0[v] = p0 + m; v1[v] = m + p3;
                }
                float m0 = v0[1] + v0[2], m1 = v1[1] + v1[2];
                SXX[0][0] = v0[0] + m0; SXX[0][1] = m0 + v0[3];
                SXX[1][0] = v1[0] + m1; SXX[1][1] = m1 + v1[3];
            }

            #pragma unroll
            for (int dr = 0; dr < 2; ++dr) {
                float Ao[2], Bo[2];
                #pragma unroll
                for (int dc = 0; dc < 2; ++dc) {
                    float sxv = SX[dr][dc], syv = SY[dr][dc];
                    // A = (sxy - sx*sy/9) / (sxx - sx*sx/9 + 9*eps); b = (sy - A*sx)/9
                    float t   = sxv * (-1.0f / 9.0f);
                    float num = fmaf(t, syv, SXY[dr][dc]);
                    float den = fmaf(t, sxv, SXX[dr][dc]) + 9e-4f;
                    float A = __fdividef(num, den);
                    float B = (syv - A * sxv) * (1.0f / 9.0f);
                    if (!inner) {
                        int gy = gy0 + r0 + dr - 1;
                        int gx = gx0 + q0 + dc - 1;
                        if (gy < 0 || gy >= H || gx < 0 || gx >= W) { A = 0.0f; B = 0.0f; }
                    }
                    Ao[dc] = A; Bo[dc] = B;
                }
                *(float2*)&sA[(r0 + dr) * SAW + q0] = make_float2(Ao[0], Ao[1]);
                *(float2*)&sB[(r0 + dr) * SAW + q0] = make_float2(Bo[0], Bo[1]);
            }
        }
    }
    __syncthreads();

    // ---- stage 3: 8 directional convs + argmin, 2x2 outputs per thread ----
    float* __restrict__ po = out + (size_t)c * H * W;
    const int ty  = tid >> 4;
    const int tx  = tid & 15;
    const int oy0 = ty * 2, ox0 = tx * 2;

    // row partial sums over 4 A/b rows: pairs (0,1),(1,2),(2,3), triples (0..2),(1..3)
    float pA01[4], pA12[4], pA23[4], tA012[4], tA123[4];
    float pB01[4], pB12[4], pB23[4], tB012[4], tB123[4];
    #pragma unroll
    for (int u = 0; u < 4; ++u) {
        const float* ba = &sA[(oy0 + u) * SAW + ox0];
        float2 a01 = *(const float2*)ba;
        float2 a23 = *(const float2*)(ba + 2);
        pA01[u]  = a01.x + a01.y;
        pA12[u]  = a01.y + a23.x;
        pA23[u]  = a23.x + a23.y;
        tA012[u] = pA01[u] + a23.x;
        tA123[u] = pA12[u] + a23.y;
    }
    #pragma unroll
    for (int u = 0; u < 4; ++u) {
        const float* bb = &sB[(oy0 + u) * SAW + ox0];
        float2 b01 = *(const float2*)bb;
        float2 b23 = *(const float2*)(bb + 2);
        pB01[u]  = b01.x + b01.y;
        pB12[u]  = b01.y + b23.x;
        pB23[u]  = b23.x + b23.y;
        tB012[u] = pB01[u] + b23.x;
        tB123[u] = pB12[u] + b23.y;
    }

    float2 imr0 = *(const float2*)&sx[(oy0 + 2) * SXW + ox0 + 2];
    float2 imr1 = *(const float2*)&sx[(oy0 + 3) * SXW + ox0 + 2];
    const float i6 = 1.0f / 6.0f;
    const float i4 = 0.25f;

    #pragma unroll
    for (int vr = 0; vr < 2; ++vr) {
        float res[2];
        #pragma unroll
        for (int vc = 0; vc < 2; ++vc) {
            // hl/hr/ha for rows vr..vr+2 at column offset vc
            float hlA0 = vc ? pA12[vr]     : pA01[vr];
            float hlA1 = vc ? pA12[vr + 1] : pA01[vr + 1];
            float hlA2 = vc ? pA12[vr + 2] : pA01[vr + 2];
            float hrA0 = vc ? pA23[vr]     : pA12[vr];
            float hrA1 = vc ? pA23[vr + 1] : pA12[vr + 1];
            float hrA2 = vc ? pA23[vr + 2] : pA12[vr + 2];
            float haA0 = vc ? tA123[vr]     : tA012[vr];
            float haA1 = vc ? tA123[vr + 1] : tA012[vr + 1];
            float haA2 = vc ? tA123[vr + 2] : tA012[vr + 2];

            float hlB0 = vc ? pB12[vr]     : pB01[vr];
            float hlB1 = vc ? pB12[vr + 1] : pB01[vr + 1];
            float hlB2 = vc ? pB12[vr + 2] : pB01[vr + 2];
            float hrB0 = vc ? pB23[vr]     : pB12[vr];
            float hrB1 = vc ? pB23[vr + 1] : pB12[vr + 1];
            float hrB2 = vc ? pB23[vr + 2] : pB12[vr + 2];
            float haB0 = vc ? tB123[vr]     : tB012[vr];
            float haB1 = vc ? tB123[vr + 1] : tB012[vr + 1];
            float haB2 = vc ? tB123[vr + 2] : tB012[vr + 2];

            float im = vr ? (vc ? imr1.y : imr1.x) : (vc ? imr0.y : imr0.x);

            float best = 3.4e38f;
            float val  = 0.0f;
            #define CAND(ae, be) { float ck = fmaf((ae), im, (be)); \
                                   float dk = fabsf(ck - im);       \
                                   if (dk < best) { best = dk; val = ck; } }
            CAND((hlA0 + hlA1 + hlA2) * i6, (hlB0 + hlB1 + hlB2) * i6);  // L
            CAND((hrA0 + hrA1 + hrA2) * i6, (hrB0 + hrB1 + hrB2) * i6);  // R
            CAND((haA0 + haA1) * i6,        (haB0 + haB1) * i6);          // U
            CAND((haA1 + haA2) * i6,        (haB1 + haB2) * i6);          // D
            CAND((hlA0 + hlA1) * i4,        (hlB0 + hlB1) * i4);          // NW
            CAND((hrA0 + hrA1) * i4,        (hrB0 + hrB1) * i4);          // NE
            CAND((hlA1 + hlA2) * i4,        (hlB1 + hlB2) * i4);          // SW
            CAND((hrA1 + hrA2) * i4,        (hrB1 + hrB2) * i4);          // SE
            #undef CAND

            res[vc] = fminf(fmaxf(truncf(val), 0.0f), 255.0f);
        }
        *(float2*)(po + (size_t)(gy0 + oy0 + vr) * W + (gx0 + ox0)) = make_float2(res[0], res[1]);
    }
}

extern "C" void kernel_launch(void* const* d_in, const int* in_sizes, int n_in,
                              void* d_out, int out_size)
{
    const float* lrx = (const float*)d_in[0];
    const float* lry = (const float*)d_in[1];
    // d_in[2] (hr_x) is unused by the reference computation.
    float* out = (float*)d_out;

    const int H = 2048, W = 2048;
    dim3 block(256);
    dim3 grid(W / TILE, H / TILE, 3);
    fgf_kernel<<<grid, block>>>(lrx, lry, out, H, W);
}

// round 3
// speedup vs baseline: 1.7051x; 1.0559x over previous
#include <cuda_runtime.h>
#include <cuda_bf16.h>
#include <math.h>

// Fused FastGuidedFilter, 64x32 tile, 2x4 per-thread coarsening, LDS.128 aligned.
//   box3x3(replicate) on lr_x, lr_y, xy, xx -> A, b   (stage 2)
//   8 directional 3x3 convs (zero pad) of A, b; argmin residual (stage 3)
//   out = clip(trunc(best), 0, 255).  hr_x unused by reference.

#define TW 64
#define TH 32
#define SXW 72   // input smem stride (36 rows x 68 cols used)
#define SAW 68   // A/b smem stride (34 rows x 66 cols used)

__global__ __launch_bounds__(256, 2)
void fgf_kernel(const float* __restrict__ lrx,
                const float* __restrict__ lry,
                float* __restrict__ out,
                int H, int W)
{
    __shared__ float sx[36 * SXW];
    __shared__ float sy[36 * SXW];
    __shared__ float sA[34 * SAW];
    __shared__ float sB[34 * SAW];

    const int tid = threadIdx.x;
    const int c   = blockIdx.z;
    const int gx0 = blockIdx.x * TW;
    const int gy0 = blockIdx.y * TH;
    const float* __restrict__ px = lrx + (size_t)c * H * W;
    const float* __restrict__ py = lry + (size_t)c * H * W;

    const bool xin = (blockIdx.x > 0) && (blockIdx.x < gridDim.x - 1);
    const bool yin = (blockIdx.y > 0) && (blockIdx.y < gridDim.y - 1);
    const bool inner = xin && yin;

    // ---- stage 1: load 36x68 halo tile (clamp == replicate pad) ----
    if (xin) {
        // 34 float2 per row x 36 rows = 1224 vector loads
        #pragma unroll
        for (int it = 0; it < 5; ++it) {
            int i = tid + it * 256;
            if (i < 1224) {
                int r = i / 34;
                int q = (i - r * 34) * 2;
                int gy = gy0 + r - 2; gy = max(0, min(H - 1, gy));
                const float2 vx = *(const float2*)(px + (size_t)gy * W + (gx0 - 2) + q);
                const float2 vy = *(const float2*)(py + (size_t)gy * W + (gx0 - 2) + q);
                *(float2*)&sx[r * SXW + q] = vx;
                *(float2*)&sy[r * SXW + q] = vy;
            }
        }
    } else {
        for (int i = tid; i < 36 * 68; i += 256) {
            int r = i / 68;
            int q = i - r * 68;
            int gy = gy0 + r - 2; gy = max(0, min(H - 1, gy));
            int gx = gx0 + q - 2; gx = max(0, min(W - 1, gx));
            size_t g = (size_t)gy * W + gx;
            sx[r * SXW + q] = px[g];
            sy[r * SXW + q] = py[g];
        }
    }
    __syncthreads();

    // ---- stage 2: A,b on 34x66 grid, 2x4 per thread (17x17 chunks) ----
    #pragma unroll
    for (int it = 0; it < 2; ++it) {
        int ci = tid + it * 256;
        if (ci < 289) {
            int cr = ci / 17;
            int cq = ci - cr * 17;
            int r0 = cr * 2, q0 = cq * 4;   // A/b coords; window = input rows r0..r0+3, cols q0..q0+5

            float xv[4][6], yv[4][6];
            #pragma unroll
            for (int u = 0; u < 4; ++u) {
                const float* bx = &sx[(r0 + u) * SXW + q0];
                const float* by = &sy[(r0 + u) * SXW + q0];
                float4 x4 = *(const float4*)bx;
                float2 x2 = *(const float2*)(bx + 4);
                float4 y4 = *(const float4*)by;
                float2 y2 = *(const float2*)(by + 4);
                xv[u][0] = x4.x; xv[u][1] = x4.y; xv[u][2] = x4.z; xv[u][3] = x4.w; xv[u][4] = x2.x; xv[u][5] = x2.y;
                yv[u][0] = y4.x; yv[u][1] = y4.y; yv[u][2] = y4.z; yv[u][3] = y4.w; yv[u][4] = y2.x; yv[u][5] = y2.y;
            }

            // box sums for 4 quantities: x, y, x*y, x*x
            float SX[2][4], SY[2][4], SXY[2][4], SXX[2][4];
            {
                float v0[6], v1[6];
                #pragma unroll
                for (int v = 0; v < 6; ++v) { float m = xv[1][v] + xv[2][v]; v0[v] = xv[0][v] + m; v1[v] = m + xv[3][v]; }
                #pragma unroll
                for (int d = 0; d < 4; ++d) { SX[0][d] = v0[d] + v0[d+1] + v0[d+2]; SX[1][d] = v1[d] + v1[d+1] + v1[d+2]; }
            }
            {
                float v0[6], v1[6];
                #pragma unroll
                for (int v = 0; v < 6; ++v) { float m = yv[1][v] + yv[2][v]; v0[v] = yv[0][v] + m; v1[v] = m + yv[3][v]; }
                #pragma unroll
                for (int d = 0; d < 4; ++d) { SY[0][d] = v0[d] + v0[d+1] + v0[d+2]; SY[1][d] = v1[d] + v1[d+1] + v1[d+2]; }
            }
            {
                float v0[6], v1[6];
                #pragma unroll
                for (int v = 0; v < 6; ++v) {
                    float p0 = xv[0][v] * yv[0][v], p1 = xv[1][v] * yv[1][v];
                    float p2 = xv[2][v] * yv[2][v], p3 = xv[3][v] * yv[3][v];
                    float m = p1 + p2; v0[v] = p0 + m; v1[v] = m + p3;
                }
                #pragma unroll
                for (int d = 0; d < 4; ++d) { SXY[0][d] = v0[d] + v0[d+1] + v0[d+2]; SXY[1][d] = v1[d] + v1[d+1] + v1[d+2]; }
            }
            {
                float v0[6], v1[6];
                #pragma unroll
                for (int v = 0; v < 6; ++v) {
                    float p0 = xv[0][v] * xv[0][v], p1 = xv[1][v] * xv[1][v];
                    float p2 = xv[2][v] * xv[2][v], p3 = xv[3][v] * xv[3][v];
                    float m = p1 + p2; v0[v] = p0 + m; v1[v] = m + p3;
                }
                #pragma unroll
                for (int d = 0; d < 4; ++d) { SXX[0][d] = v0[d] + v0[d+1] + v0[d+2]; SXX[1][d] = v1[d] + v1[d+1] + v1[d+2]; }
            }

            #pragma unroll
            for (int dr = 0; dr < 2; ++dr) {
                float Ao[4], Bo[4];
                #pragma unroll
                for (int dc = 0; dc < 4; ++dc) {
                    float sxv = SX[dr][dc], syv = SY[dr][dc];
                    // A = (sxy - sx*sy/9) / (sxx - sx*sx/9 + 9*eps); b = (sy - A*sx)/9
                    float t   = sxv * (-1.0f / 9.0f);
                    float num = fmaf(t, syv, SXY[dr][dc]);
                    float den = fmaf(t, sxv, SXX[dr][dc]) + 9e-4f;
                    float A = __fdividef(num, den);
                    float B = (syv - A * sxv) * (1.0f / 9.0f);
                    if (!inner) {
                        int gy = gy0 + r0 + dr - 1;
                        int gx = gx0 + q0 + dc - 1;
                        if (gy < 0 || gy >= H || gx < 0 || gx >= W) { A = 0.0f; B = 0.0f; }
                    }
                    Ao[dc] = A; Bo[dc] = B;
                }
                *(float4*)&sA[(r0 + dr) * SAW + q0] = make_float4(Ao[0], Ao[1], Ao[2], Ao[3]);
                *(float4*)&sB[(r0 + dr) * SAW + q0] = make_float4(Bo[0], Bo[1], Bo[2], Bo[3]);
            }
        }
    }
    __syncthreads();

    // ---- stage 3: 8 directional convs + argmin, 2x4 outputs per thread ----
    float* __restrict__ po = out + (size_t)c * H * W;
    const int ty  = tid >> 4;        // 0..15
    const int tx  = tid & 15;        // 0..15
    const int oy0 = ty * 2, ox0 = tx * 4;

    // load 4x6 A/b window
    float av[4][6], bv[4][6];
    #pragma unroll
    for (int u = 0; u < 4; ++u) {
        const float* ba = &sA[(oy0 + u) * SAW + ox0];
        float4 a4 = *(const float4*)ba;
        float2 a2 = *(const float2*)(ba + 4);
        av[u][0] = a4.x; av[u][1] = a4.y; av[u][2] = a4.z; av[u][3] = a4.w; av[u][4] = a2.x; av[u][5] = a2.y;
    }
    #pragma unroll
    for (int u = 0; u < 4; ++u) {
        const float* bb = &sB[(oy0 + u) * SAW + ox0];
        float4 b4 = *(const float4*)bb;
        float2 b2 = *(const float2*)(bb + 4);
        bv[u][0] = b4.x; bv[u][1] = b4.y; bv[u][2] = b4.z; bv[u][3] = b4.w; bv[u][4] = b2.x; bv[u][5] = b2.y;
    }

    // vertical pairs and triples (6-wide vectors)
    float PA[3][6], TA[2][6], PB[3][6], TB[2][6];
    #pragma unroll
    for (int v = 0; v < 6; ++v) {
        PA[0][v] = av[0][v] + av[1][v];
        PA[1][v] = av[1][v] + av[2][v];
        PA[2][v] = av[2][v] + av[3][v];
        TA[0][v] = PA[0][v] + av[2][v];
        TA[1][v] = PA[1][v] + av[3][v];
        PB[0][v] = bv[0][v] + bv[1][v];
        PB[1][v] = bv[1][v] + bv[2][v];
        PB[2][v] = bv[2][v] + bv[3][v];
        TB[0][v] = PB[0][v] + bv[2][v];
        TB[1][v] = PB[1][v] + bv[3][v];
    }

    const float i6 = 1.0f / 6.0f;
    const float i4 = 0.25f;

    #pragma unroll
    for (int vr = 0; vr < 2; ++vr) {
        // horizontal partials for this output row
        float hpTopA[5], hpBotA[5], hpTA[5], htTopA[4], htBotA[4];
        float hpTopB[5], hpBotB[5], hpTB[5], htTopB[4], htBotB[4];
        #pragma unroll
        for (int q = 0; q < 5; ++q) {
            hpTopA[q] = PA[vr][q] + PA[vr][q+1];
            hpBotA[q] = PA[vr+1][q] + PA[vr+1][q+1];
            hpTA[q]   = TA[vr][q] + TA[vr][q+1];
            hpTopB[q] = PB[vr][q] + PB[vr][q+1];
            hpBotB[q] = PB[vr+1][q] + PB[vr+1][q+1];
            hpTB[q]   = TB[vr][q] + TB[vr][q+1];
        }
        #pragma unroll
        for (int q = 0; q < 4; ++q) {
            htTopA[q] = hpTopA[q] + PA[vr][q+2];
            htBotA[q] = hpBotA[q] + PA[vr+1][q+2];
            htTopB[q] = hpTopB[q] + PB[vr][q+2];
            htBotB[q] = hpBotB[q] + PB[vr+1][q+2];
        }

        const float* imrow = &sx[(oy0 + 2 + vr) * SXW + ox0 + 2];
        float2 i01 = *(const float2*)imrow;
        float2 i23 = *(const float2*)(imrow + 2);
        float imv[4] = { i01.x, i01.y, i23.x, i23.y };

        float res[4];
        #pragma unroll
        for (int vc = 0; vc < 4; ++vc) {
            float im = imv[vc];
            float best = 3.4e38f;
            float val  = 0.0f;
            #define CAND(ae, be) { float ck = fmaf((ae), im, (be)); \
                                   float dk = fabsf(ck - im);       \
                                   if (dk < best) { best = dk; val = ck; } }
            CAND(hpTA[vc]    * i6, hpTB[vc]    * i6);   // L
            CAND(hpTA[vc+1]  * i6, hpTB[vc+1]  * i6);   // R
            CAND(htTopA[vc]  * i6, htTopB[vc]  * i6);   // U
            CAND(htBotA[vc]  * i6, htBotB[vc]  * i6);   // D
            CAND(hpTopA[vc]  * i4, hpTopB[vc]  * i4);   // NW
            CAND(hpTopA[vc+1]* i4, hpTopB[vc+1]* i4);   // NE
            CAND(hpBotA[vc]  * i4, hpBotB[vc]  * i4);   // SW
            CAND(hpBotA[vc+1]* i4, hpBotB[vc+1]* i4);   // SE
            #undef CAND
            res[vc] = fminf(fmaxf(truncf(val), 0.0f), 255.0f);
        }
        *(float4*)(po + (size_t)(gy0 + oy0 + vr) * W + (gx0 + ox0)) =
            make_float4(res[0], res[1], res[2], res[3]);
    }
}

extern "C" void kernel_launch(void* const* d_in, const int* in_sizes, int n_in,
                              void* d_out, int out_size)
{
    const float* lrx = (const float*)d_in[0];
    const float* lry = (const float*)d_in[1];
    // d_in[2] (hr_x) is unused by the reference computation.
    float* out = (float*)d_out;

    const int H = 2048, W = 2048;
    dim3 block(256);
    dim3 grid(W / TW, H / TH, 3);
    fgf_kernel<<<grid, block>>>(lrx, lry, out, H, W);
}

// round 5
// speedup vs baseline: 1.7321x; 1.0159x over previous
#include <cuda_runtime.h>
#include <cuda_bf16.h>
#include <math.h>

// Fused FastGuidedFilter, 62x30 tile, perfectly balanced stage-2 (1 chunk/thread).
//   box3x3(replicate) on lr_x, lr_y, xy, xx -> A, b   (stage 2)
//   8 directional 3x3 convs (zero pad) of A, b; argmin residual (stage 3)
//   out = clip(trunc(best), 0, 255).  hr_x unused by reference.
// Output stores are float2 (gx0 = 62*bx is even but may be 2 mod 4, so float4 would fault).

#define TW 62
#define TH 30
#define SXW 68   // input smem stride (34 rows x 66 cols used)
#define SAW 64   // A/b smem stride (32 rows x 64 cols, exact)

__global__ __launch_bounds__(256, 3)
void fgf_kernel(const float* __restrict__ lrx,
                const float* __restrict__ lry,
                float* __restrict__ out,
                int H, int W)
{
    __shared__ float sx[34 * SXW];
    __shared__ float sy[34 * SXW];
    __shared__ float sA[32 * SAW + 8];   // +8 pad: stage-3 edge group reads 2 past row end
    __shared__ float sB[32 * SAW + 8];

    const int tid = threadIdx.x;
    const int c   = blockIdx.z;
    const int gx0 = blockIdx.x * TW;
    const int gy0 = blockIdx.y * TH;
    const float* __restrict__ px = lrx + (size_t)c * H * W;
    const float* __restrict__ py = lry + (size_t)c * H * W;

    const bool xin = (gx0 >= 2) && (gx0 + TW + 2 <= W);
    const bool yin = (gy0 >= 2) && (gy0 + TH + 2 <= H);
    const bool inner = xin && yin;

    // ---- stage 1: load 34x66 halo tile (clamp == replicate pad) ----
    if (xin) {
        // 33 float2 per row x 34 rows = 1122 vector loads; gx0-2 even -> 8B aligned
        #pragma unroll
        for (int it = 0; it < 5; ++it) {
            int i = tid + it * 256;
            if (i < 1122) {
                int r = i / 33;
                int q = (i - r * 33) * 2;
                int gy = gy0 + r - 2; gy = max(0, min(H - 1, gy));
                const float2 vx = *(const float2*)(px + (size_t)gy * W + (gx0 - 2) + q);
                const float2 vy = *(const float2*)(py + (size_t)gy * W + (gx0 - 2) + q);
                *(float2*)&sx[r * SXW + q] = vx;
                *(float2*)&sy[r * SXW + q] = vy;
            }
        }
    } else {
        for (int i = tid; i < 34 * 66; i += 256) {
            int r = i / 66;
            int q = i - r * 66;
            int gy = gy0 + r - 2; gy = max(0, min(H - 1, gy));
            int gx = gx0 + q - 2; gx = max(0, min(W - 1, gx));
            size_t g = (size_t)gy * W + gx;
            sx[r * SXW + q] = px[g];
            sy[r * SXW + q] = py[g];
        }
    }
    __syncthreads();

    // ---- stage 2: A,b on exact 32x64 grid, one 2x4 chunk per thread ----
    {
        const int cr = tid >> 4;          // 0..15
        const int cq = tid & 15;          // 0..15
        const int r0 = cr * 2, q0 = cq * 4;

        float xv[4][6], yv[4][6];
        #pragma unroll
        for (int u = 0; u < 4; ++u) {
            const float* bx = &sx[(r0 + u) * SXW + q0];
            const float* by = &sy[(r0 + u) * SXW + q0];
            float4 x4 = *(const float4*)bx;
            float2 x2 = *(const float2*)(bx + 4);
            float4 y4 = *(const float4*)by;
            float2 y2 = *(const float2*)(by + 4);
            xv[u][0] = x4.x; xv[u][1] = x4.y; xv[u][2] = x4.z; xv[u][3] = x4.w; xv[u][4] = x2.x; xv[u][5] = x2.y;
            yv[u][0] = y4.x; yv[u][1] = y4.y; yv[u][2] = y4.z; yv[u][3] = y4.w; yv[u][4] = y2.x; yv[u][5] = y2.y;
        }

        float SX[2][4], SY[2][4], SXY[2][4], SXX[2][4];
        {
            float v0[6], v1[6];
            #pragma unroll
            for (int v = 0; v < 6; ++v) { float m = xv[1][v] + xv[2][v]; v0[v] = xv[0][v] + m; v1[v] = m + xv[3][v]; }
            #pragma unroll
            for (int d = 0; d < 4; ++d) { SX[0][d] = v0[d] + v0[d+1] + v0[d+2]; SX[1][d] = v1[d] + v1[d+1] + v1[d+2]; }
        }
        {
            float v0[6], v1[6];
            #pragma unroll
            for (int v = 0; v < 6; ++v) { float m = yv[1][v] + yv[2][v]; v0[v] = yv[0][v] + m; v1[v] = m + yv[3][v]; }
            #pragma unroll
            for (int d = 0; d < 4; ++d) { SY[0][d] = v0[d] + v0[d+1] + v0[d+2]; SY[1][d] = v1[d] + v1[d+1] + v1[d+2]; }
        }
        {
            float v0[6], v1[6];
            #pragma unroll
            for (int v = 0; v < 6; ++v) {
                float p0 = xv[0][v] * yv[0][v], p1 = xv[1][v] * yv[1][v];
                float p2 = xv[2][v] * yv[2][v], p3 = xv[3][v] * yv[3][v];
                float m = p1 + p2; v0[v] = p0 + m; v1[v] = m + p3;
            }
            #pragma unroll
            for (int d = 0; d < 4; ++d) { SXY[0][d] = v0[d] + v0[d+1] + v0[d+2]; SXY[1][d] = v1[d] + v1[d+1] + v1[d+2]; }
        }
        {
            float v0[6], v1[6];
            #pragma unroll
            for (int v = 0; v < 6; ++v) {
                float p0 = xv[0][v] * xv[0][v], p1 = xv[1][v] * xv[1][v];
                float p2 = xv[2][v] * xv[2][v], p3 = xv[3][v] * xv[3][v];
                float m = p1 + p2; v0[v] = p0 + m; v1[v] = m + p3;
            }
            #pragma unroll
            for (int d = 0; d < 4; ++d) { SXX[0][d] = v0[d] + v0[d+1] + v0[d+2]; SXX[1][d] = v1[d] + v1[d+1] + v1[d+2]; }
        }

        #pragma unroll
        for (int dr = 0; dr < 2; ++dr) {
            float Ao[4], Bo[4];
            #pragma unroll
            for (int dc = 0; dc < 4; ++dc) {
                float sxv = SX[dr][dc], syv = SY[dr][dc];
                // A = (sxy - sx*sy/9) / (sxx - sx*sx/9 + 9*eps); b = (sy - A*sx)/9
                float t   = sxv * (-1.0f / 9.0f);
                float num = fmaf(t, syv, SXY[dr][dc]);
                float den = fmaf(t, sxv, SXX[dr][dc]) + 9e-4f;
                float A = __fdividef(num, den);
                float B = (syv - A * sxv) * (1.0f / 9.0f);
                if (!inner) {
                    int gy = gy0 + r0 + dr - 1;
                    int gx = gx0 + q0 + dc - 1;
                    if (gy < 0 || gy >= H || gx < 0 || gx >= W) { A = 0.0f; B = 0.0f; }
                }
                Ao[dc] = A; Bo[dc] = B;
            }
            *(float4*)&sA[(r0 + dr) * SAW + q0] = make_float4(Ao[0], Ao[1], Ao[2], Ao[3]);
            *(float4*)&sB[(r0 + dr) * SAW + q0] = make_float4(Bo[0], Bo[1], Bo[2], Bo[3]);
        }
    }
    __syncthreads();

    // ---- stage 3: 8 directional convs + argmin, 2x4 outputs per thread ----
    const int maxy = min(TH, H - gy0);
    const int maxx = min(TW, W - gx0);
    const int ty  = tid >> 4;        // 0..15
    const int tx  = tid & 15;        // 0..15
    const int oy0 = ty * 2, ox0 = tx * 4;

    if (oy0 >= maxy || ox0 >= maxx) return;   // no syncs after this point

    float* __restrict__ po = out + (size_t)c * H * W;

    // load 4x6 A/b window (edge col-group reads 2 words into the pad)
    float av[4][6], bv[4][6];
    #pragma unroll
    for (int u = 0; u < 4; ++u) {
        const float* ba = &sA[(oy0 + u) * SAW + ox0];
        float4 a4 = *(const float4*)ba;
        float2 a2 = *(const float2*)(ba + 4);
        av[u][0] = a4.x; av[u][1] = a4.y; av[u][2] = a4.z; av[u][3] = a4.w; av[u][4] = a2.x; av[u][5] = a2.y;
    }
    #pragma unroll
    for (int u = 0; u < 4; ++u) {
        const float* bb = &sB[(oy0 + u) * SAW + ox0];
        float4 b4 = *(const float4*)bb;
        float2 b2 = *(const float2*)(bb + 4);
        bv[u][0] = b4.x; bv[u][1] = b4.y; bv[u][2] = b4.z; bv[u][3] = b4.w; bv[u][4] = b2.x; bv[u][5] = b2.y;
    }

    // vertical pairs and triples
    float PA[3][6], TA[2][6], PB[3][6], TB[2][6];
    #pragma unroll
    for (int v = 0; v < 6; ++v) {
        PA[0][v] = av[0][v] + av[1][v];
        PA[1][v] = av[1][v] + av[2][v];
        PA[2][v] = av[2][v] + av[3][v];
        TA[0][v] = PA[0][v] + av[2][v];
        TA[1][v] = PA[1][v] + av[3][v];
        PB[0][v] = bv[0][v] + bv[1][v];
        PB[1][v] = bv[1][v] + bv[2][v];
        PB[2][v] = bv[2][v] + bv[3][v];
        TB[0][v] = PB[0][v] + bv[2][v];
        TB[1][v] = PB[1][v] + bv[3][v];
    }

    const float i6 = 1.0f / 6.0f;
    const float i4 = 0.25f;

    #pragma unroll
    for (int vr = 0; vr < 2; ++vr) {
        const int oy = oy0 + vr;
        if (oy >= maxy) break;

        float hpTopA[5], hpBotA[5], hpTA[5], htTopA[4], htBotA[4];
        float hpTopB[5], hpBotB[5], hpTB[5], htTopB[4], htBotB[4];
        #pragma unroll
        for (int q = 0; q < 5; ++q) {
            hpTopA[q] = PA[vr][q] + PA[vr][q+1];
            hpBotA[q] = PA[vr+1][q] + PA[vr+1][q+1];
            hpTA[q]   = TA[vr][q] + TA[vr][q+1];
            hpTopB[q] = PB[vr][q] + PB[vr][q+1];
            hpBotB[q] = PB[vr+1][q] + PB[vr+1][q+1];
            hpTB[q]   = TB[vr][q] + TB[vr][q+1];
        }
        #pragma unroll
        for (int q = 0; q < 4; ++q) {
            htTopA[q] = hpTopA[q] + PA[vr][q+2];
            htBotA[q] = hpBotA[q] + PA[vr+1][q+2];
            htTopB[q] = hpTopB[q] + PB[vr][q+2];
            htBotB[q] = hpBotB[q] + PB[vr+1][q+2];
        }

        const float* imrow = &sx[(oy0 + 2 + vr) * SXW + ox0 + 2];
        float2 i01 = *(const float2*)imrow;
        float2 i23 = *(const float2*)(imrow + 2);
        float imv[4] = { i01.x, i01.y, i23.x, i23.y };

        float res[4];
        #pragma unroll
        for (int vc = 0; vc < 4; ++vc) {
            float im = imv[vc];
            float best = 3.4e38f;
            float val  = 0.0f;
            #define CAND(ae, be) { float ck = fmaf((ae), im, (be)); \
                                   float dk = fabsf(ck - im);       \
                                   if (dk < best) { best = dk; val = ck; } }
            CAND(hpTA[vc]    * i6, hpTB[vc]    * i6);   // L
            CAND(hpTA[vc+1]  * i6, hpTB[vc+1]  * i6);   // R
            CAND(htTopA[vc]  * i6, htTopB[vc]  * i6);   // U
            CAND(htBotA[vc]  * i6, htBotB[vc]  * i6);   // D
            CAND(hpTopA[vc]  * i4, hpTopB[vc]  * i4);   // NW
            CAND(hpTopA[vc+1]* i4, hpTopB[vc+1]* i4);   // NE
            CAND(hpBotA[vc]  * i4, hpBotB[vc]  * i4);   // SW
            CAND(hpBotA[vc+1]* i4, hpBotB[vc+1]* i4);   // SE
            #undef CAND
            res[vc] = fminf(fmaxf(truncf(val), 0.0f), 255.0f);
        }

        float* prow = po + (size_t)(gy0 + oy) * W + (gx0 + ox0);
        if (ox0 + 4 <= maxx) {
            // gx0+ox0 is even -> float2 stores are 8B-aligned (float4 would not be 16B-aligned)
            *(float2*)prow       = make_float2(res[0], res[1]);
            *(float2*)(prow + 2) = make_float2(res[2], res[3]);
        } else {
            #pragma unroll
            for (int vc = 0; vc < 4; ++vc)
                if (ox0 + vc < maxx) prow[vc] = res[vc];
        }
    }
}

extern "C" void kernel_launch(void* const* d_in, const int* in_sizes, int n_in,
                              void* d_out, int out_size)
{
    const float* lrx = (const float*)d_in[0];
    const float* lry = (const float*)d_in[1];
    // d_in[2] (hr_x) is unused by the reference computation.
    float* out = (float*)d_out;

    const int H = 2048, W = 2048;
    dim3 block(256);
    dim3 grid((W + TW - 1) / TW, (H + TH - 1) / TH, 3);
    fgf_kernel<<<grid, block>>>(lrx, lry, out, H, W);
}

// round 6
// speedup vs baseline: 1.8317x; 1.0575x over previous
#include <cuda_runtime.h>
#include <cuda_bf16.h>
#include <math.h>

// Fused FastGuidedFilter, 62x30 tile, register-lean restructure for 4 blocks/SM.
//   box3x3(replicate) on lr_x, lr_y, xy, xx -> A, b   (stage 2, row-streamed)
//   8 directional 3x3 convs (zero pad) of A, b; argmin residual (stage 3, per-row)
//   out = clip(trunc(best), 0, 255).  hr_x unused by reference.

#define TW 62
#define TH 30
#define SXW 68   // input smem stride (34 rows x 66 cols used)
#define SAW 64   // A/b smem stride (32 rows x 64 cols, exact)

__global__ __launch_bounds__(256, 4)
void fgf_kernel(const float* __restrict__ lrx,
                const float* __restrict__ lry,
                float* __restrict__ out,
                int H, int W)
{
    __shared__ float sx[34 * SXW];
    __shared__ float sy[34 * SXW];
    __shared__ float sA[32 * SAW + 8];   // +8 pad: stage-3 edge group reads 2 past row end
    __shared__ float sB[32 * SAW + 8];

    const int tid = threadIdx.x;
    const int c   = blockIdx.z;
    const int gx0 = blockIdx.x * TW;
    const int gy0 = blockIdx.y * TH;
    const float* __restrict__ px = lrx + (size_t)c * H * W;
    const float* __restrict__ py = lry + (size_t)c * H * W;

    const bool xin = (gx0 >= 2) && (gx0 + TW + 2 <= W);
    const bool yin = (gy0 >= 2) && (gy0 + TH + 2 <= H);
    const bool inner = xin && yin;

    // ---- stage 1: load 34x66 halo tile (clamp == replicate pad) ----
    if (xin) {
        #pragma unroll
        for (int it = 0; it < 5; ++it) {
            int i = tid + it * 256;
            if (i < 1122) {                       // 33 float2 per row x 34 rows
                int r = i / 33;
                int q = (i - r * 33) * 2;
                int gy = gy0 + r - 2; gy = max(0, min(H - 1, gy));
                const float2 vx = *(const float2*)(px + (size_t)gy * W + (gx0 - 2) + q);
                const float2 vy = *(const float2*)(py + (size_t)gy * W + (gx0 - 2) + q);
                *(float2*)&sx[r * SXW + q] = vx;
                *(float2*)&sy[r * SXW + q] = vy;
            }
        }
    } else {
        for (int i = tid; i < 34 * 66; i += 256) {
            int r = i / 66;
            int q = i - r * 66;
            int gy = gy0 + r - 2; gy = max(0, min(H - 1, gy));
            int gx = gx0 + q - 2; gx = max(0, min(W - 1, gx));
            size_t g = (size_t)gy * W + gx;
            sx[r * SXW + q] = px[g];
            sy[r * SXW + q] = py[g];
        }
    }
    __syncthreads();

    // ---- stage 2: A,b on exact 32x64 grid, one 2x4 chunk per thread, row-streamed ----
    {
        const int cr = tid >> 4;          // 0..15
        const int cq = tid & 15;          // 0..15
        const int r0 = cr * 2, q0 = cq * 4;

        // S0: box sums for A-row r0 (input rows r0..r0+2); S1: for A-row r0+1 (rows r0+1..r0+3)
        float S0x[4], S0y[4], S0xy[4], S0xx[4];
        float S1x[4], S1y[4], S1xy[4], S1xx[4];

        #pragma unroll
        for (int u = 0; u < 4; ++u) {
            const float* bx = &sx[(r0 + u) * SXW + q0];
            const float* by = &sy[(r0 + u) * SXW + q0];
            float4 x4 = *(const float4*)bx;
            float2 x2 = *(const float2*)(bx + 4);
            float4 y4 = *(const float4*)by;
            float2 y2 = *(const float2*)(by + 4);
            float xr[6] = { x4.x, x4.y, x4.z, x4.w, x2.x, x2.y };
            float yr[6] = { y4.x, y4.y, y4.z, y4.w, y2.x, y2.y };

            float hx[4], hy[4], hxy[4], hxx[4];
            #pragma unroll
            for (int d = 0; d < 4; ++d) {
                hx[d]  = xr[d] + xr[d+1] + xr[d+2];
                hy[d]  = yr[d] + yr[d+1] + yr[d+2];
                hxy[d] = fmaf(xr[d], yr[d], fmaf(xr[d+1], yr[d+1], xr[d+2] * yr[d+2]));
                hxx[d] = fmaf(xr[d], xr[d], fmaf(xr[d+1], xr[d+1], xr[d+2] * xr[d+2]));
            }
            if (u == 0) {
                #pragma unroll
                for (int d = 0; d < 4; ++d) { S0x[d] = hx[d]; S0y[d] = hy[d]; S0xy[d] = hxy[d]; S0xx[d] = hxx[d]; }
            } else if (u == 1) {
                #pragma unroll
                for (int d = 0; d < 4; ++d) {
                    S0x[d] += hx[d]; S0y[d] += hy[d]; S0xy[d] += hxy[d]; S0xx[d] += hxx[d];
                    S1x[d]  = hx[d]; S1y[d]  = hy[d]; S1xy[d]  = hxy[d]; S1xx[d]  = hxx[d];
                }
            } else if (u == 2) {
                #pragma unroll
                for (int d = 0; d < 4; ++d) {
                    S0x[d] += hx[d]; S0y[d] += hy[d]; S0xy[d] += hxy[d]; S0xx[d] += hxx[d];
                    S1x[d] += hx[d]; S1y[d] += hy[d]; S1xy[d] += hxy[d]; S1xx[d] += hxx[d];
                }
            } else {
                #pragma unroll
                for (int d = 0; d < 4; ++d) {
                    S1x[d] += hx[d]; S1y[d] += hy[d]; S1xy[d] += hxy[d]; S1xx[d] += hxx[d];
                }
            }
        }

        #pragma unroll
        for (int dr = 0; dr < 2; ++dr) {
            float Ao[4], Bo[4];
            #pragma unroll
            for (int dc = 0; dc < 4; ++dc) {
                float sxv = dr ? S1x[dc]  : S0x[dc];
                float syv = dr ? S1y[dc]  : S0y[dc];
                float sxy = dr ? S1xy[dc] : S0xy[dc];
                float sxx = dr ? S1xx[dc] : S0xx[dc];
                // A = (sxy - sx*sy/9) / (sxx - sx*sx/9 + 9*eps); b = (sy - A*sx)/9
                float t   = sxv * (-1.0f / 9.0f);
                float num = fmaf(t, syv, sxy);
                float den = fmaf(t, sxv, sxx) + 9e-4f;
                float A = __fdividef(num, den);
                float B = (syv - A * sxv) * (1.0f / 9.0f);
                if (!inner) {
                    int gy = gy0 + r0 + dr - 1;
                    int gx = gx0 + q0 + dc - 1;
                    if (gy < 0 || gy >= H || gx < 0 || gx >= W) { A = 0.0f; B = 0.0f; }
                }
                Ao[dc] = A; Bo[dc] = B;
            }
            *(float4*)&sA[(r0 + dr) * SAW + q0] = make_float4(Ao[0], Ao[1], Ao[2], Ao[3]);
            *(float4*)&sB[(r0 + dr) * SAW + q0] = make_float4(Bo[0], Bo[1], Bo[2], Bo[3]);
        }
    }
    __syncthreads();

    // ---- stage 3: 8 directional convs + argmin, 2 rows x 4 cols per thread ----
    const int maxy = min(TH, H - gy0);
    const int maxx = min(TW, W - gx0);
    const int ty  = tid >> 4;        // 0..15
    const int tx  = tid & 15;        // 0..15
    const int oy0 = ty * 2, ox0 = tx * 4;

    if (oy0 >= maxy || ox0 >= maxx) return;   // no syncs after this point

    float* __restrict__ po = out + (size_t)c * H * W;
    const float i6 = 1.0f / 6.0f;
    const float i4 = 0.25f;

    #pragma unroll
    for (int vr = 0; vr < 2; ++vr) {
        const int oy = oy0 + vr;
        if (oy >= maxy) break;

        // vertical combos over the 3 A/b rows for this output row (6-wide)
        float vpTA[6], vpBA[6], vtA[6];     // top pair, bottom pair, triple
        float vpTB[6], vpBB[6], vtB[6];
        {
            const int rbase = oy0 + vr;
            const float* a0p = &sA[(rbase    ) * SAW + ox0];
            const float* a1p = &sA[(rbase + 1) * SAW + ox0];
            const float* a2p = &sA[(rbase + 2) * SAW + ox0];
            #pragma unroll
            for (int half = 0; half < 2; ++half) {
                // half 0: cols 0..3 via float4; half 1: cols 4..5 via float2
                if (half == 0) {
                    float4 r0 = *(const float4*)a0p;
                    float4 r1 = *(const float4*)a1p;
                    float4 r2 = *(const float4*)a2p;
                    vpTA[0] = r0.x + r1.x; vpBA[0] = r1.x + r2.x; vtA[0] = vpTA[0] + r2.x;
                    vpTA[1] = r0.y + r1.y; vpBA[1] = r1.y + r2.y; vtA[1] = vpTA[1] + r2.y;
                    vpTA[2] = r0.z + r1.z; vpBA[2] = r1.z + r2.z; vtA[2] = vpTA[2] + r2.z;
                    vpTA[3] = r0.w + r1.w; vpBA[3] = r1.w + r2.w; vtA[3] = vpTA[3] + r2.w;
                } else {
                    float2 r0 = *(const float2*)(a0p + 4);
                    float2 r1 = *(const float2*)(a1p + 4);
                    float2 r2 = *(const float2*)(a2p + 4);
                    vpTA[4] = r0.x + r1.x; vpBA[4] = r1.x + r2.x; vtA[4] = vpTA[4] + r2.x;
                    vpTA[5] = r0.y + r1.y; vpBA[5] = r1.y + r2.y; vtA[5] = vpTA[5] + r2.y;
                }
            }
            const float* b0p = &sB[(rbase    ) * SAW + ox0];
            const float* b1p = &sB[(rbase + 1) * SAW + ox0];
            const float* b2p = &sB[(rbase + 2) * SAW + ox0];
            #pragma unroll
            for (int half = 0; half < 2; ++half) {
                if (half == 0) {
                    float4 r0 = *(const float4*)b0p;
                    float4 r1 = *(const float4*)b1p;
                    float4 r2 = *(const float4*)b2p;
                    vpTB[0] = r0.x + r1.x; vpBB[0] = r1.x + r2.x; vtB[0] = vpTB[0] + r2.x;
                    vpTB[1] = r0.y + r1.y; vpBB[1] = r1.y + r2.y; vtB[1] = vpTB[1] + r2.y;
                    vpTB[2] = r0.z + r1.z; vpBB[2] = r1.z + r2.z; vtB[2] = vpTB[2] + r2.z;
                    vpTB[3] = r0.w + r1.w; vpBB[3] = r1.w + r2.w; vtB[3] = vpTB[3] + r2.w;
                } else {
                    float2 r0 = *(const float2*)(b0p + 4);
                    float2 r1 = *(const float2*)(b1p + 4);
                    float2 r2 = *(const float2*)(b2p + 4);
                    vpTB[4] = r0.x + r1.x; vpBB[4] = r1.x + r2.x; vtB[4] = vpTB[4] + r2.x;
                    vpTB[5] = r0.y + r1.y; vpBB[5] = r1.y + r2.y; vtB[5] = vpTB[5] + r2.y;
                }
            }
        }

        // horizontal sums
        float hpTopA[5], hpBotA[5], hpTA[5], htTopA[4], htBotA[4];
        float hpTopB[5], hpBotB[5], hpTB[5], htTopB[4], htBotB[4];
        #pragma unroll
        for (int q = 0; q < 5; ++q) {
            hpTopA[q] = vpTA[q] + vpTA[q+1];
            hpBotA[q] = vpBA[q] + vpBA[q+1];
            hpTA[q]   = vtA[q]  + vtA[q+1];
            hpTopB[q] = vpTB[q] + vpTB[q+1];
            hpBotB[q] = vpBB[q] + vpBB[q+1];
            hpTB[q]   = vtB[q]  + vtB[q+1];
        }
        #pragma unroll
        for (int q = 0; q < 4; ++q) {
            htTopA[q] = hpTopA[q] + vpTA[q+2];
            htBotA[q] = hpBotA[q] + vpBA[q+2];
            htTopB[q] = hpTopB[q] + vpTB[q+2];
            htBotB[q] = hpBotB[q] + vpBB[q+2];
        }

        const float* imrow = &sx[(oy0 + 2 + vr) * SXW + ox0 + 2];
        float2 i01 = *(const float2*)imrow;
        float2 i23 = *(const float2*)(imrow + 2);
        float imv[4] = { i01.x, i01.y, i23.x, i23.y };

        float res[4];
        #pragma unroll
        for (int vc = 0; vc < 4; ++vc) {
            float im = imv[vc];
            float best = 3.4e38f;
            float val  = 0.0f;
            #define CAND(ae, be) { float ck = fmaf((ae), im, (be)); \
                                   float dk = fabsf(ck - im);       \
                                   if (dk < best) { best = dk; val = ck; } }
            CAND(hpTA[vc]    * i6, hpTB[vc]    * i6);   // L
            CAND(hpTA[vc+1]  * i6, hpTB[vc+1]  * i6);   // R
            CAND(htTopA[vc]  * i6, htTopB[vc]  * i6);   // U
            CAND(htBotA[vc]  * i6, htBotB[vc]  * i6);   // D
            CAND(hpTopA[vc]  * i4, hpTopB[vc]  * i4);   // NW
            CAND(hpTopA[vc+1]* i4, hpTopB[vc+1]* i4);   // NE
            CAND(hpBotA[vc]  * i4, hpBotB[vc]  * i4);   // SW
            CAND(hpBotA[vc+1]* i4, hpBotB[vc+1]* i4);   // SE
            #undef CAND
            res[vc] = fminf(fmaxf(truncf(val), 0.0f), 255.0f);
        }

        float* prow = po + (size_t)(gy0 + oy) * W + (gx0 + ox0);
        if (ox0 + 4 <= maxx) {
            // gx0+ox0 is even -> float2 stores are 8B-aligned (float4 may be only 8B-aligned)
            *(float2*)prow       = make_float2(res[0], res[1]);
            *(float2*)(prow + 2) = make_float2(res[2], res[3]);
        } else {
            #pragma unroll
            for (int vc = 0; vc < 4; ++vc)
                if (ox0 + vc < maxx) prow[vc] = res[vc];
        }
    }
}

extern "C" void kernel_launch(void* const* d_in, const int* in_sizes, int n_in,
                              void* d_out, int out_size)
{
    const float* lrx = (const float*)d_in[0];
    const float* lry = (const float*)d_in[1];
    // d_in[2] (hr_x) is unused by the reference computation.
    float* out = (float*)d_out;

    const int H = 2048, W = 2048;
    dim3 block(256);
    dim3 grid((W + TW - 1) / TW, (H + TH - 1) / TH, 3);
    fgf_kernel<<<grid, block>>>(lrx, lry, out, H, W);
}

// round 7
// speedup vs baseline: 1.8425x; 1.0059x over previous
#include <cuda_runtime.h>
#include <cuda_bf16.h>
#include <math.h>

// Fused FastGuidedFilter, 62x30 tile.
//   stage 2: box3x3(replicate) stats -> A,b stored INTERLEAVED (a,b) in smem
//   stage 3: 8 directional convs via pre-shifted sums + grouped argmin
//            d_k = ((sumA - n)*im + sumB)/n ; compare 3|g4| vs 2|g6| cross-group
//   out = clip(trunc(best), 0, 255).  hr_x unused by reference.

#define TW 62
#define TH 30
#define SXW 68    // input smem stride (34 rows x 66 cols used)
#define SABW 136  // interleaved A/b stride: 64 cols x 2 floats + 8 pad

__global__ __launch_bounds__(256, 4)
void fgf_kernel(const float* __restrict__ lrx,
                const float* __restrict__ lry,
                float* __restrict__ out,
                int H, int W)
{
    __shared__ float sx[34 * SXW];
    __shared__ float sy[34 * SXW];
    __shared__ float sAB[32 * SABW + 8];   // (a,b) interleaved; pad for edge overreads

    const int tid = threadIdx.x;
    const int c   = blockIdx.z;
    const int gx0 = blockIdx.x * TW;
    const int gy0 = blockIdx.y * TH;
    const float* __restrict__ px = lrx + (size_t)c * H * W;
    const float* __restrict__ py = lry + (size_t)c * H * W;

    const bool xin = (gx0 >= 2) && (gx0 + TW + 2 <= W);
    const bool yin = (gy0 >= 2) && (gy0 + TH + 2 <= H);
    const bool inner = xin && yin;

    // ---- stage 1: load 34x66 halo tile (clamp == replicate pad) ----
    if (xin) {
        #pragma unroll
        for (int it = 0; it < 5; ++it) {
            int i = tid + it * 256;
            if (i < 1122) {                       // 33 float2 per row x 34 rows
                int r = i / 33;
                int q = (i - r * 33) * 2;
                int gy = gy0 + r - 2; gy = max(0, min(H - 1, gy));
                const float2 vx = *(const float2*)(px + (size_t)gy * W + (gx0 - 2) + q);
                const float2 vy = *(const float2*)(py + (size_t)gy * W + (gx0 - 2) + q);
                *(float2*)&sx[r * SXW + q] = vx;
                *(float2*)&sy[r * SXW + q] = vy;
            }
        }
    } else {
        for (int i = tid; i < 34 * 66; i += 256) {
            int r = i / 66;
            int q = i - r * 66;
            int gy = gy0 + r - 2; gy = max(0, min(H - 1, gy));
            int gx = gx0 + q - 2; gx = max(0, min(W - 1, gx));
            size_t g = (size_t)gy * W + gx;
            sx[r * SXW + q] = px[g];
            sy[r * SXW + q] = py[g];
        }
    }
    __syncthreads();

    // ---- stage 2: A,b on exact 32x64 grid, one 2x4 chunk per thread, row-streamed ----
    {
        const int cr = tid >> 4;          // 0..15
        const int cq = tid & 15;          // 0..15
        const int r0 = cr * 2, q0 = cq * 4;

        float S0x[4], S0y[4], S0xy[4], S0xx[4];
        float S1x[4], S1y[4], S1xy[4], S1xx[4];

        #pragma unroll
        for (int u = 0; u < 4; ++u) {
            const float* bx = &sx[(r0 + u) * SXW + q0];
            const float* by = &sy[(r0 + u) * SXW + q0];
            float4 x4 = *(const float4*)bx;
            float2 x2 = *(const float2*)(bx + 4);
            float4 y4 = *(const float4*)by;
            float2 y2 = *(const float2*)(by + 4);
            float xr[6] = { x4.x, x4.y, x4.z, x4.w, x2.x, x2.y };
            float yr[6] = { y4.x, y4.y, y4.z, y4.w, y2.x, y2.y };

            float hx[4], hy[4], hxy[4], hxx[4];
            #pragma unroll
            for (int d = 0; d < 4; ++d) {
                hx[d]  = xr[d] + xr[d+1] + xr[d+2];
                hy[d]  = yr[d] + yr[d+1] + yr[d+2];
                hxy[d] = fmaf(xr[d], yr[d], fmaf(xr[d+1], yr[d+1], xr[d+2] * yr[d+2]));
                hxx[d] = fmaf(xr[d], xr[d], fmaf(xr[d+1], xr[d+1], xr[d+2] * xr[d+2]));
            }
            if (u == 0) {
                #pragma unroll
                for (int d = 0; d < 4; ++d) { S0x[d] = hx[d]; S0y[d] = hy[d]; S0xy[d] = hxy[d]; S0xx[d] = hxx[d]; }
            } else if (u == 1) {
                #pragma unroll
                for (int d = 0; d < 4; ++d) {
                    S0x[d] += hx[d]; S0y[d] += hy[d]; S0xy[d] += hxy[d]; S0xx[d] += hxx[d];
                    S1x[d]  = hx[d]; S1y[d]  = hy[d]; S1xy[d]  = hxy[d]; S1xx[d]  = hxx[d];
                }
            } else if (u == 2) {
                #pragma unroll
                for (int d = 0; d < 4; ++d) {
                    S0x[d] += hx[d]; S0y[d] += hy[d]; S0xy[d] += hxy[d]; S0xx[d] += hxx[d];
                    S1x[d] += hx[d]; S1y[d] += hy[d]; S1xy[d] += hxy[d]; S1xx[d] += hxx[d];
                }
            } else {
                #pragma unroll
                for (int d = 0; d < 4; ++d) {
                    S1x[d] += hx[d]; S1y[d] += hy[d]; S1xy[d] += hxy[d]; S1xx[d] += hxx[d];
                }
            }
        }

        #pragma unroll
        for (int dr = 0; dr < 2; ++dr) {
            float Ao[4], Bo[4];
            #pragma unroll
            for (int dc = 0; dc < 4; ++dc) {
                float sxv = dr ? S1x[dc]  : S0x[dc];
                float syv = dr ? S1y[dc]  : S0y[dc];
                float sxy = dr ? S1xy[dc] : S0xy[dc];
                float sxx = dr ? S1xx[dc] : S0xx[dc];
                float t   = sxv * (-1.0f / 9.0f);
                float num = fmaf(t, syv, sxy);
                float den = fmaf(t, sxv, sxx) + 9e-4f;
                float A = __fdividef(num, den);
                float B = (syv - A * sxv) * (1.0f / 9.0f);
                if (!inner) {
                    int gy = gy0 + r0 + dr - 1;
                    int gx = gx0 + q0 + dc - 1;
                    if (gy < 0 || gy >= H || gx < 0 || gx >= W) { A = 0.0f; B = 0.0f; }
                }
                Ao[dc] = A; Bo[dc] = B;
            }
            float* prow = &sAB[(r0 + dr) * SABW + q0 * 2];
            *(float4*)prow       = make_float4(Ao[0], Bo[0], Ao[1], Bo[1]);
            *(float4*)(prow + 4) = make_float4(Ao[2], Bo[2], Ao[3], Bo[3]);
        }
    }
    __syncthreads();

    // ---- stage 3: grouped argmin over 8 directions, 2 rows x 4 cols per thread ----
    const int maxy = min(TH, H - gy0);
    const int maxx = min(TW, W - gx0);
    const int ty  = tid >> 4;        // 0..15
    const int tx  = tid & 15;        // 0..15
    const int oy0 = ty * 2, ox0 = tx * 4;

    if (oy0 >= maxy || ox0 >= maxx) return;   // no syncs after this point

    float* __restrict__ po = out + (size_t)c * H * W;

    #pragma unroll
    for (int vr = 0; vr < 2; ++vr) {
        const int oy = oy0 + vr;
        if (oy >= maxy) break;

        // load 3 interleaved rows (cols ox0..ox0+5 of A and b)
        const float* r0p = &sAB[(oy    ) * SABW + ox0 * 2];
        const float* r1p = &sAB[(oy + 1) * SABW + ox0 * 2];
        const float* r2p = &sAB[(oy + 2) * SABW + ox0 * 2];
        float4 q00 = *(const float4*)r0p, q01 = *(const float4*)(r0p + 4), q02 = *(const float4*)(r0p + 8);
        float4 q10 = *(const float4*)r1p, q11 = *(const float4*)(r1p + 4), q12 = *(const float4*)(r1p + 8);
        float4 q20 = *(const float4*)r2p, q21 = *(const float4*)(r2p + 4), q22 = *(const float4*)(r2p + 8);

        float a0[6] = { q00.x, q00.z, q01.x, q01.z, q02.x, q02.z };
        float b0[6] = { q00.y, q00.w, q01.y, q01.w, q02.y, q02.w };
        float a1[6] = { q10.x, q10.z, q11.x, q11.z, q12.x, q12.z };
        float b1[6] = { q10.y, q10.w, q11.y, q11.w, q12.y, q12.w };
        float a2[6] = { q20.x, q20.z, q21.x, q21.z, q22.x, q22.z };
        float b2[6] = { q20.y, q20.w, q21.y, q21.w, q22.y, q22.w };

        // vertical combos
        float vpTa[6], vpBa[6], vta[6], vpTb[6], vpBb[6], vtb[6];
        #pragma unroll
        for (int v = 0; v < 6; ++v) {
            vpTa[v] = a0[v] + a1[v];
            vpBa[v] = a1[v] + a2[v];
            vta[v]  = vpTa[v] + a2[v];
            vpTb[v] = b0[v] + b1[v];
            vpBb[v] = b1[v] + b2[v];
            vtb[v]  = vpTb[v] + b2[v];
        }

        // horizontal sums; A-sums pre-shifted by their normalizer
        float hL6a[5], hT4a[5], hB4a[5];      // A: L/R triple-6; NW/NE top pair-4; SW/SE bottom pair-4
        float hLb[5],  hTb[5],  hBb[5];       // matching B sums (unshifted)
        float hU6a[4], hD6a[4], hUb[4], hDb[4];
        #pragma unroll
        for (int q = 0; q < 5; ++q) {
            hL6a[q] = vta[q] + vta[q+1] - 6.0f;
            hLb[q]  = vtb[q] + vtb[q+1];
            float tT = vpTa[q] + vpTa[q+1];
            float tB = vpBa[q] + vpBa[q+1];
            hT4a[q] = tT - 4.0f;
            hB4a[q] = tB - 4.0f;
            hTb[q]  = vpTb[q] + vpTb[q+1];
            hBb[q]  = vpBb[q] + vpBb[q+1];
        }
        #pragma unroll
        for (int q = 0; q < 4; ++q) {
            hU6a[q] = hT4a[q] + vpTa[q+2] - 2.0f;   // (top pair - 4) + third - 2 == triple - 6
            hD6a[q] = hB4a[q] + vpBa[q+2] - 2.0f;
            hUb[q]  = hTb[q] + vpTb[q+2];
            hDb[q]  = hBb[q] + vpBb[q+2];
        }

        const float* imrow = &sx[(oy0 + 2 + vr) * SXW + ox0 + 2];
        float2 i01 = *(const float2*)imrow;
        float2 i23 = *(const float2*)(imrow + 2);
        float imv[4] = { i01.x, i01.y, i23.x, i23.y };

        float res[4];
        #pragma unroll
        for (int vc = 0; vc < 4; ++vc) {
            float im = imv[vc];
            // g = (sumA - n)*im + sumB ; d = g/n ; candidates in reference order
            float g0 = fmaf(hL6a[vc],   im, hLb[vc]);     // L
            float g1 = fmaf(hL6a[vc+1], im, hLb[vc+1]);   // R
            float g2 = fmaf(hU6a[vc],   im, hUb[vc]);     // U
            float g3 = fmaf(hD6a[vc],   im, hDb[vc]);     // D
            float h0 = fmaf(hT4a[vc],   im, hTb[vc]);     // NW
            float h1 = fmaf(hT4a[vc+1], im, hTb[vc+1]);   // NE
            float h2 = fmaf(hB4a[vc],   im, hBb[vc]);     // SW
            float h3 = fmaf(hB4a[vc+1], im, hBb[vc+1]);   // SE

            float d6 = fabsf(g0), b6 = g0;
            if (fabsf(g1) < d6) { d6 = fabsf(g1); b6 = g1; }
            if (fabsf(g2) < d6) { d6 = fabsf(g2); b6 = g2; }
            if (fabsf(g3) < d6) { d6 = fabsf(g3); b6 = g3; }
            float d4 = fabsf(h0), b4 = h0;
            if (fabsf(h1) < d4) { d4 = fabsf(h1); b4 = h1; }
            if (fabsf(h2) < d4) { d4 = fabsf(h2); b4 = h2; }
            if (fabsf(h3) < d4) { d4 = fabsf(h3); b4 = h3; }

            // cross-group: |g4|/4 < |g6|/6  <=>  3*d4 < 2*d6  (tie -> /6 group, preserving order)
            float v6 = fmaf(b6, 1.0f / 6.0f, im);
            float v4 = fmaf(b4, 0.25f, im);
            float val = (3.0f * d4 < 2.0f * d6) ? v4 : v6;
            res[vc] = fminf(fmaxf(truncf(val), 0.0f), 255.0f);
        }

        float* prow = po + (size_t)(gy0 + oy) * W + (gx0 + ox0);
        if (ox0 + 4 <= maxx) {
            // gx0+ox0 is even -> float2 stores are 8B-aligned (16B alignment not guaranteed)
            *(float2*)prow       = make_float2(res[0], res[1]);
            *(float2*)(prow + 2) = make_float2(res[2], res[3]);
        } else {
            #pragma unroll
            for (int vc = 0; vc < 4; ++vc)
                if (ox0 + vc < maxx) prow[vc] = res[vc];
        }
    }
}

extern "C" void kernel_launch(void* const* d_in, const int* in_sizes, int n_in,
                              void* d_out, int out_size)
{
    const float* lrx = (const float*)d_in[0];
    const float* lry = (const float*)d_in[1];
    // d_in[2] (hr_x) is unused by the reference computation.
    float* out = (float*)d_out;

    const int H = 2048, W = 2048;
    dim3 block(256);
    dim3 grid((W + TW - 1) / TW, (H + TH - 1) / TH, 3);
    fgf_kernel<<<grid, block>>>(lrx, lry, out, H, W);
}